// round 1
// baseline (speedup 1.0000x reference)
#include <cuda_runtime.h>
#include <cstdint>
#include <cstddef>

#define NIMG 8
#define TOPK 5000
#define NDET 100
#define CAND_CAP 16384
#define NBINS 4096
#define NANCH 49104

// ---------------- scratch (device globals; no allocation) ----------------
__device__ unsigned int      g_hist[NIMG][NBINS];
__device__ unsigned int      g_T[NIMG];
__device__ int               g_candCount[NIMG];
__device__ unsigned long long g_cand[NIMG][CAND_CAP];
__device__ float             g_topval[NIMG][TOPK];
__device__ int               g_topidx[NIMG][TOPK];
__device__ float             g_bx[NIMG][TOPK * 4];
__device__ float             g_sc[NIMG][TOPK];
__device__ int               g_cl[NIMG][TOPK];

// level constants
__constant__ int c_LN[5]     = {3317760, 829440, 207360, 51840, 12960}; // elems per image per level (cls)
__constant__ int c_CB[6]     = {0, 810, 1013, 1064, 1077, 1081};        // cumulative blocks @4096 elems/block
__constant__ int c_log2HW[5] = {12, 10, 8, 6, 4};
__constant__ int c_aOff[5]   = {0, 36864, 46080, 48384, 48960};

__device__ __forceinline__ unsigned int orderKey(float f) {
    unsigned int b = __float_as_uint(f);
    return (b & 0x80000000u) ? ~b : (b | 0x80000000u);
}

// ---------------- K0: zero histograms ----------------
__global__ void k_zero() {
    unsigned int* p = &g_hist[0][0];
    int i = blockIdx.x * blockDim.x + threadIdx.x;
    if (i < NIMG * NBINS) p[i] = 0u;
}

// ---------------- K1: per-image 12-bit histogram over all cls logits ----------------
__global__ void __launch_bounds__(256) k_hist(const float* __restrict__ c0, const float* __restrict__ c1,
                                              const float* __restrict__ c2, const float* __restrict__ c3,
                                              const float* __restrict__ c4) {
    __shared__ unsigned int sh[NBINS];
    const float* cls[5] = {c0, c1, c2, c3, c4};
    int b = blockIdx.y;
    int bx = blockIdx.x;
    int l = 0;
    while (bx >= c_CB[l + 1]) l++;
    int chunk = bx - c_CB[l];
    int n = c_LN[l];
    const float* p = cls[l] + (size_t)b * n;
    int tid = threadIdx.x;
    for (int i = tid; i < NBINS; i += 256) sh[i] = 0u;
    __syncthreads();
    int base = chunk * 4096;
#pragma unroll
    for (int it = 0; it < 4; it++) {
        int e = base + (it * 256 + tid) * 4;
        if (e < n) {
            float4 v = *(const float4*)(p + e);
            atomicAdd(&sh[orderKey(v.x) >> 20], 1u);
            atomicAdd(&sh[orderKey(v.y) >> 20], 1u);
            atomicAdd(&sh[orderKey(v.z) >> 20], 1u);
            atomicAdd(&sh[orderKey(v.w) >> 20], 1u);
        }
    }
    __syncthreads();
    for (int i = tid; i < NBINS; i += 256) {
        unsigned int c = sh[i];
        if (c) atomicAdd(&g_hist[b][i], c);
    }
}

// ---------------- K2: find threshold bin per image (suffix scan from top) ----------------
__global__ void __launch_bounds__(1024) k_thresh() {
    __shared__ unsigned int part[1024];
    int b = blockIdx.x;
    int t = threadIdx.x;
    unsigned int h[4], s = 0;
#pragma unroll
    for (int k = 0; k < 4; k++) {
        h[k] = g_hist[b][4095 - (4 * t + k)];
        s += h[k];
    }
    part[t] = s;
    unsigned int my = s;
    __syncthreads();
    for (int off = 1; off < 1024; off <<= 1) {
        unsigned int v = (t >= off) ? part[t - off] : 0u;
        __syncthreads();
        part[t] += v;
        __syncthreads();
    }
    unsigned int incl = part[t];
    unsigned int excl = incl - my;
    if (excl < TOPK && incl >= TOPK) {
        unsigned int run = excl;
#pragma unroll
        for (int k = 0; k < 4; k++) {
            if (run + h[k] >= TOPK) { g_T[b] = 4095 - (4 * t + k); break; }
            run += h[k];
        }
    }
    if (t == 0) g_candCount[b] = 0;
}

// ---------------- K3: compact candidates >= threshold bin, with reference flat index ----------------
__global__ void __launch_bounds__(256) k_compact(const float* __restrict__ c0, const float* __restrict__ c1,
                                                 const float* __restrict__ c2, const float* __restrict__ c3,
                                                 const float* __restrict__ c4) {
    const float* cls[5] = {c0, c1, c2, c3, c4};
    int b = blockIdx.y;
    int bx = blockIdx.x;
    int l = 0;
    while (bx >= c_CB[l + 1]) l++;
    int chunk = bx - c_CB[l];
    int n = c_LN[l];
    const float* p = cls[l] + (size_t)b * n;
    unsigned int T = g_T[b];
    int log2HW = c_log2HW[l];
    int HWm1 = (1 << log2HW) - 1;
    int aOff = c_aOff[l];
    int tid = threadIdx.x;
    int base = chunk * 4096;
#pragma unroll
    for (int it = 0; it < 4; it++) {
        int e = base + (it * 256 + tid) * 4;
        if (e < n) {
            float4 v = *(const float4*)(p + e);
            float fv[4] = {v.x, v.y, v.z, v.w};
#pragma unroll
            for (int k = 0; k < 4; k++) {
                unsigned int u = orderKey(fv[k]);
                if ((u >> 20) >= T) {
                    int off = e + k;
                    int ch = off >> log2HW;       // channel = a*90 + class
                    int r = off & HWm1;           // h*W + w
                    int a = ch / 90;
                    int c = ch - a * 90;
                    int j = (aOff + r * 9 + a) * 90 + c; // reference flattened index
                    int pos = atomicAdd(&g_candCount[b], 1);
                    if (pos < CAND_CAP)
                        g_cand[b][pos] = ((unsigned long long)u << 32) | (unsigned int)(~j);
                }
            }
        }
    }
}

// ---------------- K4: per-image bitonic sort (desc) of candidates, emit top-5000 ----------------
__global__ void __launch_bounds__(1024) k_sort() {
    extern __shared__ unsigned long long ss[];
    int b = blockIdx.x;
    int tid = threadIdx.x;
    int n = g_candCount[b];
    if (n > CAND_CAP) n = CAND_CAP;
    for (int i = tid; i < CAND_CAP; i += 1024) ss[i] = (i < n) ? g_cand[b][i] : 0ull;
    __syncthreads();
    for (int k = 2; k <= CAND_CAP; k <<= 1) {
        for (int j = k >> 1; j > 0; j >>= 1) {
            for (int i = tid; i < CAND_CAP; i += 1024) {
                int l = i ^ j;
                if (l > i) {
                    unsigned long long a = ss[i], c = ss[l];
                    bool desc = ((i & k) == 0);
                    if (desc ? (a < c) : (a > c)) { ss[i] = c; ss[l] = a; }
                }
            }
            __syncthreads();
        }
    }
    for (int i = tid; i < TOPK; i += 1024) {
        unsigned long long key = ss[i];
        unsigned int u = (unsigned int)(key >> 32);
        unsigned int j = ~((unsigned int)key);
        unsigned int bits = (u & 0x80000000u) ? (u & 0x7fffffffu) : ~u;
        g_topval[b][i] = __uint_as_float(bits);
        g_topidx[b][i] = (int)j;
    }
}

// ---------------- K5: gather box_t, decode boxes, sigmoid scores ----------------
__global__ void __launch_bounds__(256) k_decode(const float* __restrict__ b0, const float* __restrict__ b1,
                                                const float* __restrict__ b2, const float* __restrict__ b3,
                                                const float* __restrict__ b4,
                                                const float* __restrict__ anchors) {
    const float* box[5] = {b0, b1, b2, b3, b4};
    int b = blockIdx.y;
    int t = blockIdx.x * 256 + threadIdx.x;
    if (t >= TOPK) return;
    int j = g_topidx[b][t];
    int anchor = j / 90;
    int cls = j - anchor * 90;
    int l;
    if (anchor >= 48960) l = 4;
    else if (anchor >= 48384) l = 3;
    else if (anchor >= 46080) l = 2;
    else if (anchor >= 36864) l = 1;
    else l = 0;
    int idx2 = anchor - c_aOff[l];
    int cell = idx2 / 9;
    int a = idx2 - cell * 9;
    int HW = 1 << c_log2HW[l];
    const float* bp = box[l] + (size_t)b * 36 * HW;
    float ty = bp[(a * 4 + 0) * HW + cell];
    float tx = bp[(a * 4 + 1) * HW + cell];
    float th = bp[(a * 4 + 2) * HW + cell];
    float tw = bp[(a * 4 + 3) * HW + cell];
    const float* an = anchors + (size_t)anchor * 4;
    float a0 = an[0], a1 = an[1], a2 = an[2], a3 = an[3];
    float yca = (a0 + a2) * 0.5f;
    float xca = (a1 + a3) * 0.5f;
    float ha = a2 - a0;
    float wa = a3 - a1;
    float w = expf(tw) * wa;
    float h = expf(th) * ha;
    float yc = ty * ha + yca;
    float xc = tx * wa + xca;
    g_bx[b][t * 4 + 0] = xc - w * 0.5f;
    g_bx[b][t * 4 + 1] = yc - h * 0.5f;
    g_bx[b][t * 4 + 2] = xc + w * 0.5f;
    g_bx[b][t * 4 + 3] = yc + h * 0.5f;
    float v = g_topval[b][t];
    g_sc[b][t] = 1.0f / (1.0f + expf(-v));
    g_cl[b][t] = cls;
}

// ---------------- K6: per-image greedy class-aware NMS + output ----------------
// dyn smem layout:
//   [0,        80000)  float4 sb[5000]   offset boxes
//   [80000,   100000)  float  sar[5000]  areas (on offset boxes)
//   [100000,  120000)  float  ssc[5000]  mutable scores
//   [120000,  124096)  float  redv[1024]
//   [124096,  128192)  int    redi[1024]
//   [128192,  128592)  int    ssel[100]
//   [128592,  128992)  int    svalid[100]
#define NMS_SMEM 129024
__global__ void __launch_bounds__(1024) k_nms(float* __restrict__ out, const float* __restrict__ scales) {
    extern __shared__ char sm[];
    float4* sb  = (float4*)sm;
    float* sar  = (float*)(sm + 80000);
    float* ssc  = (float*)(sm + 100000);
    float* redv = (float*)(sm + 120000);
    int* redi   = (int*)(sm + 124096);
    int* ssel   = (int*)(sm + 128192);
    int* svalid = (int*)(sm + 128592);

    int b = blockIdx.x;
    int tid = threadIdx.x;

    // Phase A: max over all decoded coords
    float m = -__int_as_float(0x7f800000); // -inf
    for (int i = tid; i < TOPK * 4; i += 1024) m = fmaxf(m, g_bx[b][i]);
    redv[tid] = m;
    __syncthreads();
    for (int s = 512; s > 0; s >>= 1) {
        if (tid < s) redv[tid] = fmaxf(redv[tid], redv[tid + s]);
        __syncthreads();
    }
    float offBase = redv[0] + 1.0f;
    __syncthreads();

    // Phase B: offset boxes, areas, scores
    for (int t = tid; t < TOPK; t += 1024) {
        float x1 = g_bx[b][t * 4 + 0];
        float y1 = g_bx[b][t * 4 + 1];
        float x2 = g_bx[b][t * 4 + 2];
        float y2 = g_bx[b][t * 4 + 3];
        float off = (float)g_cl[b][t] * offBase;
        float4 bb = make_float4(x1 + off, y1 + off, x2 + off, y2 + off);
        sb[t] = bb;
        sar[t] = (bb.z - bb.x) * (bb.w - bb.y);
        ssc[t] = g_sc[b][t];
    }
    __syncthreads();

    // Phase C: 100 greedy iterations
    for (int it = 0; it < NDET; it++) {
        float bv = -__int_as_float(0x7f800000);
        int bidx = 0x7fffffff;
        for (int t = tid; t < TOPK; t += 1024) {
            float s = ssc[t];
            if (s > bv) { bv = s; bidx = t; }
        }
        redv[tid] = bv;
        redi[tid] = bidx;
        __syncthreads();
        for (int s = 512; s > 0; s >>= 1) {
            if (tid < s) {
                float v2 = redv[tid + s];
                int i2 = redi[tid + s];
                if (v2 > redv[tid] || (v2 == redv[tid] && i2 < redi[tid])) {
                    redv[tid] = v2;
                    redi[tid] = i2;
                }
            }
            __syncthreads();
        }
        int sel = redi[0];
        float sval = ssc[sel];
        float4 bi = sb[sel];
        float ai = sar[sel];
        __syncthreads();
        for (int t = tid; t < TOPK; t += 1024) {
            float4 bj = sb[t];
            float xx1 = fmaxf(bi.x, bj.x);
            float yy1 = fmaxf(bi.y, bj.y);
            float xx2 = fminf(bi.z, bj.z);
            float yy2 = fminf(bi.w, bj.w);
            float inter = fmaxf(xx2 - xx1, 0.0f) * fmaxf(yy2 - yy1, 0.0f);
            float iou = inter / (sar[t] + ai - inter);
            if (iou > 0.5f) ssc[t] = -1.0f;
        }
        if (tid == 0) {
            ssel[it] = sel;
            svalid[it] = (sval > 0.0f) ? 1 : 0;
        }
        __syncthreads();
    }

    // Phase D: write output rows
    if (tid < NDET) {
        int i = ssel[tid];
        float* o = out + ((size_t)b * NDET + tid) * 6;
        if (svalid[tid]) {
            float x1 = g_bx[b][i * 4 + 0];
            float y1 = g_bx[b][i * 4 + 1];
            float x2 = g_bx[b][i * 4 + 2];
            float y2 = g_bx[b][i * 4 + 3];
            float sc = g_sc[b][i];
            float cl = (float)g_cl[b][i] + 1.0f;
            float s = scales[b];
            o[0] = x1 * s;
            o[1] = y1 * s;
            o[2] = (x2 - x1) * s;
            o[3] = (y2 - y1) * s;
            o[4] = sc;
            o[5] = cl;
        } else {
            o[0] = 0.0f; o[1] = 0.0f; o[2] = 0.0f;
            o[3] = 0.0f; o[4] = 0.0f; o[5] = 0.0f;
        }
    }
}

// ---------------- host ----------------
extern "C" void kernel_launch(void* const* d_in, const int* in_sizes, int n_in,
                              void* d_out, int out_size) {
    const float* cls[5] = {nullptr, nullptr, nullptr, nullptr, nullptr};
    const float* box[5] = {nullptr, nullptr, nullptr, nullptr, nullptr};
    const float* scales = nullptr;
    const float* anchors = nullptr;
    static const int clsSizes[5] = {26542080, 6635520, 1658880, 414720, 103680};
    static const int boxSizes[5] = {1179648, 294912, 73728, 18432, 4608};
    for (int i = 0; i < n_in; i++) {
        int s = in_sizes[i];
        const float* p = (const float*)d_in[i];
        if (s == 8) { scales = p; continue; }
        if (s == 196416) { anchors = p; continue; }
        for (int l = 0; l < 5; l++) {
            if (s == clsSizes[l]) cls[l] = p;
            else if (s == boxSizes[l]) box[l] = p;
        }
    }

    cudaFuncSetAttribute(k_sort, cudaFuncAttributeMaxDynamicSharedMemorySize, CAND_CAP * 8);
    cudaFuncSetAttribute(k_nms, cudaFuncAttributeMaxDynamicSharedMemorySize, NMS_SMEM);

    k_zero<<<(NIMG * NBINS + 1023) / 1024, 1024>>>();
    k_hist<<<dim3(1081, NIMG), 256>>>(cls[0], cls[1], cls[2], cls[3], cls[4]);
    k_thresh<<<NIMG, 1024>>>();
    k_compact<<<dim3(1081, NIMG), 256>>>(cls[0], cls[1], cls[2], cls[3], cls[4]);
    k_sort<<<NIMG, 1024, CAND_CAP * 8>>>();
    k_decode<<<dim3((TOPK + 255) / 256, NIMG), 256>>>(box[0], box[1], box[2], box[3], box[4], anchors);
    k_nms<<<NIMG, 1024, NMS_SMEM>>>((float*)d_out, scales);
}

// round 2
// speedup vs baseline: 1.3169x; 1.3169x over previous
#include <cuda_runtime.h>
#include <cstdint>
#include <cstddef>

#define NIMG 8
#define TOPK 5000
#define NDET 100
#define CAND_CAP 16384
#define PRE_CAP 49152
#define PRE_KEY 0xC0200000u   /* orderKey(2.5f) */
#define HIST_LO 3072
#define NMS_NW 157            /* ceil(5000/32) */

// ---------------- scratch (device globals; no allocation) ----------------
__device__ unsigned int       g_hist[NIMG][4096];
__device__ int                g_preCount[NIMG];
__device__ unsigned long long g_pre[NIMG][PRE_CAP];
__device__ unsigned int       g_T[NIMG];
__device__ int                g_fbImg[NIMG];   // per-image: compact must rescan raw data
__device__ int                g_fbHist[NIMG];  // per-image: need full histogram + re-threshold
__device__ int                g_candCount[NIMG];
__device__ unsigned long long g_cand[NIMG][CAND_CAP];
__device__ float              g_topval[NIMG][TOPK];
__device__ int                g_topidx[NIMG][TOPK];
__device__ float              g_bx[NIMG][TOPK * 4];
__device__ float              g_sc[NIMG][TOPK];
__device__ int                g_cl[NIMG][TOPK];

__constant__ int c_LN[5]     = {3317760, 829440, 207360, 51840, 12960};
__constant__ int c_CB[6]     = {0, 810, 1013, 1064, 1077, 1081};
__constant__ int c_log2HW[5] = {12, 10, 8, 6, 4};
__constant__ int c_aOff[5]   = {0, 36864, 46080, 48384, 48960};

__device__ __forceinline__ unsigned int orderKey(float f) {
    unsigned int b = __float_as_uint(f);
    return (b & 0x80000000u) ? ~b : (b | 0x80000000u);
}

// ---------------- K0: reset scratch ----------------
__global__ void k_zero() {
    int i = blockIdx.x * blockDim.x + threadIdx.x;
    if (i < NIMG * 4096) (&g_hist[0][0])[i] = 0u;
    if (i < NIMG) {
        g_preCount[i] = 0;
        g_fbImg[i] = 0;
        g_fbHist[i] = 0;
    }
}

// ---------------- K1: fused pass — histogram (top 1024 bins) + prefilter compact ----------------
__global__ void __launch_bounds__(256) k_fused(const float* __restrict__ c0, const float* __restrict__ c1,
                                               const float* __restrict__ c2, const float* __restrict__ c3,
                                               const float* __restrict__ c4) {
    __shared__ unsigned int sh[1024];
    const float* cls[5] = {c0, c1, c2, c3, c4};
    int b = blockIdx.y;
    int bx = blockIdx.x;
    int l = 0;
    while (bx >= c_CB[l + 1]) l++;
    int chunk = bx - c_CB[l];
    int n = c_LN[l];
    const float* p = cls[l] + (size_t)b * n;
    int log2HW = c_log2HW[l];
    int HWm1 = (1 << log2HW) - 1;
    int aOff = c_aOff[l];
    int tid = threadIdx.x;
    for (int i = tid; i < 1024; i += 256) sh[i] = 0u;
    __syncthreads();

    int base = chunk * 4096 + tid * 4;
    float4 v[4];
    bool ok[4];
#pragma unroll
    for (int it = 0; it < 4; it++) {
        int e = base + it * 1024;
        ok[it] = (e < n);
        if (ok[it]) v[it] = *(const float4*)(p + e);
    }
#pragma unroll
    for (int it = 0; it < 4; it++) {
        if (!ok[it]) continue;
        int e = base + it * 1024;
        float fv[4] = {v[it].x, v[it].y, v[it].z, v[it].w};
#pragma unroll
        for (int k = 0; k < 4; k++) {
            unsigned int u = orderKey(fv[k]);
            if (u >= PRE_KEY) {
                atomicAdd(&sh[(u >> 20) - HIST_LO], 1u);
                int off = e + k;
                int ch = off >> log2HW;
                int r = off & HWm1;
                int a = ch / 90;
                int c = ch - a * 90;
                int j = (aOff + r * 9 + a) * 90 + c;   // reference flattened index
                int pos = atomicAdd(&g_preCount[b], 1);
                if (pos < PRE_CAP)
                    g_pre[b][pos] = ((unsigned long long)u << 32) | (unsigned int)(~j);
            }
        }
    }
    __syncthreads();
    for (int i = tid; i < 1024; i += 256) {
        unsigned int c = sh[i];
        if (c) atomicAdd(&g_hist[b][HIST_LO + i], c);
    }
}

// ---------------- K2: threshold from top 1024 bins; detect fallback needs ----------------
__global__ void __launch_bounds__(1024) k_thresh() {
    __shared__ unsigned int part[1024];
    int b = blockIdx.x;
    int t = threadIdx.x;
    unsigned int h = g_hist[b][4095 - t];
    part[t] = h;
    __syncthreads();
    for (int off = 1; off < 1024; off <<= 1) {
        unsigned int vv = (t >= off) ? part[t - off] : 0u;
        __syncthreads();
        part[t] += vv;
        __syncthreads();
    }
    unsigned int incl = part[t];
    unsigned int excl = incl - h;
    if (excl < TOPK && incl >= TOPK) g_T[b] = 4095 - t;
    if (t == 1023) {
        g_candCount[b] = 0;
        if (incl < TOPK) {            // threshold below prefilter region: need full path
            g_fbHist[b] = 1;
            g_fbImg[b] = 1;
        } else if (g_preCount[b] > PRE_CAP) { // staging overflowed: rescan raw for compact
            g_fbImg[b] = 1;
        }
    }
}

// ---------------- K3: fallback full histogram of elements below PRE_KEY (no-op normally) ----
__global__ void __launch_bounds__(256) k_fb_hist(const float* __restrict__ c0, const float* __restrict__ c1,
                                                 const float* __restrict__ c2, const float* __restrict__ c3,
                                                 const float* __restrict__ c4) {
    int b = blockIdx.y;
    if (!g_fbHist[b]) return;
    __shared__ unsigned int sh[4096];
    const float* cls[5] = {c0, c1, c2, c3, c4};
    int bx = blockIdx.x;
    int l = 0;
    while (bx >= c_CB[l + 1]) l++;
    int chunk = bx - c_CB[l];
    int n = c_LN[l];
    const float* p = cls[l] + (size_t)b * n;
    int tid = threadIdx.x;
    for (int i = tid; i < 4096; i += 256) sh[i] = 0u;
    __syncthreads();
    int base = chunk * 4096;
#pragma unroll
    for (int it = 0; it < 4; it++) {
        int e = base + (it * 256 + tid) * 4;
        if (e < n) {
            float4 v = *(const float4*)(p + e);
            float fv[4] = {v.x, v.y, v.z, v.w};
#pragma unroll
            for (int k = 0; k < 4; k++) {
                unsigned int u = orderKey(fv[k]);
                if (u < PRE_KEY) atomicAdd(&sh[u >> 20], 1u);
            }
        }
    }
    __syncthreads();
    for (int i = tid; i < 4096; i += 256) {
        unsigned int c = sh[i];
        if (c) atomicAdd(&g_hist[b][i], c);
    }
}

// ---------------- K4: fallback threshold over all 4096 bins (no-op normally) ----------------
__global__ void __launch_bounds__(1024) k_fb_thresh() {
    int b = blockIdx.x;
    if (!g_fbHist[b]) return;
    __shared__ unsigned int part[1024];
    int t = threadIdx.x;
    unsigned int h[4], s = 0;
#pragma unroll
    for (int k = 0; k < 4; k++) {
        h[k] = g_hist[b][4095 - (4 * t + k)];
        s += h[k];
    }
    part[t] = s;
    unsigned int my = s;
    __syncthreads();
    for (int off = 1; off < 1024; off <<= 1) {
        unsigned int vv = (t >= off) ? part[t - off] : 0u;
        __syncthreads();
        part[t] += vv;
        __syncthreads();
    }
    unsigned int incl = part[t];
    unsigned int excl = incl - my;
    if (excl < TOPK && incl >= TOPK) {
        unsigned int run = excl;
#pragma unroll
        for (int k = 0; k < 4; k++) {
            if (run + h[k] >= TOPK) { g_T[b] = 4095 - (4 * t + k); break; }
            run += h[k];
        }
    }
}

// ---------------- K5: compact — from staging buffer (fast) or raw rescan (fallback) --------
#define PRE_BLOCKS (PRE_CAP / 4096)
__global__ void __launch_bounds__(256) k_compact(const float* __restrict__ c0, const float* __restrict__ c1,
                                                 const float* __restrict__ c2, const float* __restrict__ c3,
                                                 const float* __restrict__ c4) {
    int b = blockIdx.y;
    int bx = blockIdx.x;
    int tid = threadIdx.x;
    unsigned int T = g_T[b];
    if (!g_fbImg[b]) {
        if (bx >= PRE_BLOCKS) return;
        int n = g_preCount[b];
        if (n > PRE_CAP) n = PRE_CAP;
#pragma unroll
        for (int it = 0; it < 16; it++) {
            int i = bx * 4096 + it * 256 + tid;
            if (i < n) {
                unsigned long long key = g_pre[b][i];
                if ((unsigned int)(key >> 52) >= T) {
                    int pos = atomicAdd(&g_candCount[b], 1);
                    if (pos < CAND_CAP) g_cand[b][pos] = key;
                }
            }
        }
        return;
    }
    // fallback: full rescan of raw logits
    const float* cls[5] = {c0, c1, c2, c3, c4};
    int l = 0;
    while (bx >= c_CB[l + 1]) l++;
    int chunk = bx - c_CB[l];
    int n = c_LN[l];
    const float* p = cls[l] + (size_t)b * n;
    int log2HW = c_log2HW[l];
    int HWm1 = (1 << log2HW) - 1;
    int aOff = c_aOff[l];
    int base = chunk * 4096;
#pragma unroll
    for (int it = 0; it < 4; it++) {
        int e = base + (it * 256 + tid) * 4;
        if (e < n) {
            float4 v = *(const float4*)(p + e);
            float fv[4] = {v.x, v.y, v.z, v.w};
#pragma unroll
            for (int k = 0; k < 4; k++) {
                unsigned int u = orderKey(fv[k]);
                if ((u >> 20) >= T) {
                    int off = e + k;
                    int ch = off >> log2HW;
                    int r = off & HWm1;
                    int a = ch / 90;
                    int c = ch - a * 90;
                    int j = (aOff + r * 9 + a) * 90 + c;
                    int pos = atomicAdd(&g_candCount[b], 1);
                    if (pos < CAND_CAP)
                        g_cand[b][pos] = ((unsigned long long)u << 32) | (unsigned int)(~j);
                }
            }
        }
    }
}

// ---------------- K6: per-image bitonic sort (desc), runtime pow2 size ----------------
__global__ void __launch_bounds__(1024) k_sort() {
    extern __shared__ unsigned long long ss[];
    int b = blockIdx.x;
    int tid = threadIdx.x;
    int n = g_candCount[b];
    if (n > CAND_CAP) n = CAND_CAP;
    int np = 8192;
    while (np < n) np <<= 1;
    for (int i = tid; i < np; i += 1024) ss[i] = (i < n) ? g_cand[b][i] : 0ull;
    __syncthreads();
    for (int k = 2; k <= np; k <<= 1) {
        for (int j = k >> 1; j > 0; j >>= 1) {
            for (int i = tid; i < np; i += 1024) {
                int l = i ^ j;
                if (l > i) {
                    unsigned long long a = ss[i], c = ss[l];
                    bool desc = ((i & k) == 0);
                    if (desc ? (a < c) : (a > c)) { ss[i] = c; ss[l] = a; }
                }
            }
            __syncthreads();
        }
    }
    for (int i = tid; i < TOPK; i += 1024) {
        unsigned long long key = ss[i];
        unsigned int u = (unsigned int)(key >> 32);
        unsigned int j = ~((unsigned int)key);
        unsigned int bits = (u & 0x80000000u) ? (u & 0x7fffffffu) : ~u;
        g_topval[b][i] = __uint_as_float(bits);
        g_topidx[b][i] = (int)j;
    }
}

// ---------------- K7: gather box_t, decode boxes, sigmoid scores ----------------
__global__ void __launch_bounds__(256) k_decode(const float* __restrict__ b0, const float* __restrict__ b1,
                                                const float* __restrict__ b2, const float* __restrict__ b3,
                                                const float* __restrict__ b4,
                                                const float* __restrict__ anchors) {
    const float* box[5] = {b0, b1, b2, b3, b4};
    int b = blockIdx.y;
    int t = blockIdx.x * 256 + threadIdx.x;
    if (t >= TOPK) return;
    int j = g_topidx[b][t];
    int anchor = j / 90;
    int cls = j - anchor * 90;
    int l;
    if (anchor >= 48960) l = 4;
    else if (anchor >= 48384) l = 3;
    else if (anchor >= 46080) l = 2;
    else if (anchor >= 36864) l = 1;
    else l = 0;
    int idx2 = anchor - c_aOff[l];
    int cell = idx2 / 9;
    int a = idx2 - cell * 9;
    int HW = 1 << c_log2HW[l];
    const float* bp = box[l] + (size_t)b * 36 * HW;
    float ty = bp[(a * 4 + 0) * HW + cell];
    float tx = bp[(a * 4 + 1) * HW + cell];
    float th = bp[(a * 4 + 2) * HW + cell];
    float tw = bp[(a * 4 + 3) * HW + cell];
    const float* an = anchors + (size_t)anchor * 4;
    float a0 = an[0], a1 = an[1], a2 = an[2], a3 = an[3];
    float yca = (a0 + a2) * 0.5f;
    float xca = (a1 + a3) * 0.5f;
    float ha = a2 - a0;
    float wa = a3 - a1;
    float w = expf(tw) * wa;
    float h = expf(th) * ha;
    float yc = ty * ha + yca;
    float xc = tx * wa + xca;
    g_bx[b][t * 4 + 0] = xc - w * 0.5f;
    g_bx[b][t * 4 + 1] = yc - h * 0.5f;
    g_bx[b][t * 4 + 2] = xc + w * 0.5f;
    g_bx[b][t * 4 + 3] = yc + h * 0.5f;
    float v = g_topval[b][t];
    g_sc[b][t] = 1.0f / (1.0f + expf(-v));
    g_cl[b][t] = cls;
}

// ---------------- K8: per-image greedy NMS via sorted-order cursor + bitmask ----------------
// dyn smem layout:
//   [0,       80000)  float4 sb[5000]
//   [80000,  100000)  float  sar[5000]
//   [100000, 100628)  uint   mask[157]
//   [100640, 101040)  int    ssel[100]
//   [101040, 101168)  float  warpmax[32]
//   [101168, 101188)  scalars: s_cur, s_bcast, s_nsel, s_done, s_off
#define NMS_SMEM 101248
__global__ void __launch_bounds__(1024) k_nms(float* __restrict__ out, const float* __restrict__ scales) {
    extern __shared__ char sm[];
    float4* sb        = (float4*)sm;
    float* sar        = (float*)(sm + 80000);
    unsigned int* msk = (unsigned int*)(sm + 100000);
    int* ssel         = (int*)(sm + 100640);
    float* warpmax    = (float*)(sm + 101040);
    int* s_cur        = (int*)(sm + 101168);
    int* s_bcast      = (int*)(sm + 101172);
    int* s_nsel       = (int*)(sm + 101176);
    int* s_done       = (int*)(sm + 101180);
    float* s_off      = (float*)(sm + 101184);

    int b = blockIdx.x;
    int tid = threadIdx.x;
    int lane = tid & 31;
    int wid = tid >> 5;

    // Phase A: max over all decoded coords (for the class-offset base)
    float m = -3.4e38f;
    for (int i = tid; i < TOPK * 4; i += 1024) m = fmaxf(m, g_bx[b][i]);
#pragma unroll
    for (int o = 16; o > 0; o >>= 1) m = fmaxf(m, __shfl_xor_sync(0xffffffffu, m, o));
    if (lane == 0) warpmax[wid] = m;
    __syncthreads();
    if (tid < 32) {
        float v = warpmax[tid];
#pragma unroll
        for (int o = 16; o > 0; o >>= 1) v = fmaxf(v, __shfl_xor_sync(0xffffffffu, v, o));
        if (tid == 0) *s_off = v + 1.0f;
    }
    __syncthreads();
    float offBase = *s_off;

    // Phase B: build offset boxes + areas; init mask/cursor
    for (int t = tid; t < TOPK; t += 1024) {
        float x1 = g_bx[b][t * 4 + 0];
        float y1 = g_bx[b][t * 4 + 1];
        float x2 = g_bx[b][t * 4 + 2];
        float y2 = g_bx[b][t * 4 + 3];
        float off = (float)g_cl[b][t] * offBase;
        float4 bb = make_float4(x1 + off, y1 + off, x2 + off, y2 + off);
        sb[t] = bb;
        sar[t] = (bb.z - bb.x) * (bb.w - bb.y);
    }
    if (tid < NMS_NW) msk[tid] = (tid == NMS_NW - 1) ? 0xFFFFFF00u : 0u;
    if (tid == 0) { *s_cur = 0; *s_nsel = 0; *s_done = 0; }
    __syncthreads();

    // Phase C: 100 greedy iterations; selection = first unsuppressed in sorted order
    for (int it = 0; it < NDET; it++) {
        if (tid == 0) {
            int sel = -1;
            int w = *s_cur;
            while (w < NMS_NW) {
                unsigned int avail = ~msk[w];
                if (avail) { sel = w * 32 + __ffs(avail) - 1; break; }
                w++;
            }
            *s_cur = w;
            *s_bcast = sel;
            if (sel >= 0) {
                msk[w] |= (1u << (sel & 31));
                ssel[it] = sel;
                *s_nsel = it + 1;
            } else {
                *s_done = 1;
            }
        }
        __syncthreads();
        if (*s_done) break;
        int sel = *s_bcast;
        float4 bi = sb[sel];
        float ai = sar[sel];
        for (int t = tid; t < TOPK; t += 1024) {
            float4 bj = sb[t];
            float xx1 = fmaxf(bi.x, bj.x);
            float yy1 = fmaxf(bi.y, bj.y);
            float xx2 = fminf(bi.z, bj.z);
            float yy2 = fminf(bi.w, bj.w);
            float inter = fmaxf(xx2 - xx1, 0.0f) * fmaxf(yy2 - yy1, 0.0f);
            float iou = inter / (sar[t] + ai - inter);
            if (iou > 0.5f) atomicOr(&msk[t >> 5], 1u << (t & 31));
        }
        __syncthreads();
    }
    __syncthreads();

    // Phase D: write output
    if (tid < NDET) {
        float* o = out + ((size_t)b * NDET + tid) * 6;
        if (tid < *s_nsel) {
            int i = ssel[tid];
            float x1 = g_bx[b][i * 4 + 0];
            float y1 = g_bx[b][i * 4 + 1];
            float x2 = g_bx[b][i * 4 + 2];
            float y2 = g_bx[b][i * 4 + 3];
            float sc = g_sc[b][i];
            float cl = (float)g_cl[b][i] + 1.0f;
            float s = scales[b];
            o[0] = x1 * s;
            o[1] = y1 * s;
            o[2] = (x2 - x1) * s;
            o[3] = (y2 - y1) * s;
            o[4] = sc;
            o[5] = cl;
        } else {
            o[0] = 0.0f; o[1] = 0.0f; o[2] = 0.0f;
            o[3] = 0.0f; o[4] = 0.0f; o[5] = 0.0f;
        }
    }
}

// ---------------- host ----------------
extern "C" void kernel_launch(void* const* d_in, const int* in_sizes, int n_in,
                              void* d_out, int out_size) {
    const float* cls[5] = {nullptr, nullptr, nullptr, nullptr, nullptr};
    const float* box[5] = {nullptr, nullptr, nullptr, nullptr, nullptr};
    const float* scales = nullptr;
    const float* anchors = nullptr;
    static const int clsSizes[5] = {26542080, 6635520, 1658880, 414720, 103680};
    static const int boxSizes[5] = {1179648, 294912, 73728, 18432, 4608};
    for (int i = 0; i < n_in; i++) {
        int s = in_sizes[i];
        const float* p = (const float*)d_in[i];
        if (s == 8) { scales = p; continue; }
        if (s == 196416) { anchors = p; continue; }
        for (int l = 0; l < 5; l++) {
            if (s == clsSizes[l]) cls[l] = p;
            else if (s == boxSizes[l]) box[l] = p;
        }
    }

    cudaFuncSetAttribute(k_sort, cudaFuncAttributeMaxDynamicSharedMemorySize, CAND_CAP * 8);
    cudaFuncSetAttribute(k_nms, cudaFuncAttributeMaxDynamicSharedMemorySize, NMS_SMEM);

    k_zero<<<(NIMG * 4096 + 1023) / 1024, 1024>>>();
    k_fused<<<dim3(1081, NIMG), 256>>>(cls[0], cls[1], cls[2], cls[3], cls[4]);
    k_thresh<<<NIMG, 1024>>>();
    k_fb_hist<<<dim3(1081, NIMG), 256>>>(cls[0], cls[1], cls[2], cls[3], cls[4]);
    k_fb_thresh<<<NIMG, 1024>>>();
    k_compact<<<dim3(1081, NIMG), 256>>>(cls[0], cls[1], cls[2], cls[3], cls[4]);
    k_sort<<<NIMG, 1024, CAND_CAP * 8>>>();
    k_decode<<<dim3((TOPK + 255) / 256, NIMG), 256>>>(box[0], box[1], box[2], box[3], box[4], anchors);
    k_nms<<<NIMG, 1024, NMS_SMEM>>>((float*)d_out, scales);
}

// round 3
// speedup vs baseline: 1.7046x; 1.2944x over previous
#include <cuda_runtime.h>
#include <cstdint>
#include <cstddef>

#define NIMG 8
#define TOPK 5000
#define NDET 100
#define CAND_CAP 16384
#define PRE_CAP 49152
#define PRE_KEY 0xC0200000u   /* orderKey(2.5f) */
#define HIST_LO 3072
#define FULLW 0xffffffffu

// ---------------- scratch (device globals; no allocation) ----------------
__device__ unsigned int       g_hist[NIMG][4096];
__device__ int                g_preCount[NIMG];
__device__ unsigned long long g_pre[NIMG][PRE_CAP];
__device__ unsigned int       g_T[NIMG];
__device__ int                g_fbImg[NIMG];
__device__ int                g_fbHist[NIMG];
__device__ int                g_candCount[NIMG];
__device__ unsigned long long g_cand[NIMG][CAND_CAP];
__device__ float              g_bx[NIMG][TOPK * 4];
__device__ float              g_sc[NIMG][TOPK];
__device__ int                g_cl[NIMG][TOPK];

__constant__ int c_LN[5]     = {3317760, 829440, 207360, 51840, 12960};
__constant__ int c_CB[6]     = {0, 810, 1013, 1064, 1077, 1081};
__constant__ int c_log2HW[5] = {12, 10, 8, 6, 4};
__constant__ int c_aOff[5]   = {0, 36864, 46080, 48384, 48960};

__device__ __forceinline__ unsigned int orderKey(float f) {
    unsigned int b = __float_as_uint(f);
    return (b & 0x80000000u) ? ~b : (b | 0x80000000u);
}

// ---------------- K0: reset scratch ----------------
__global__ void k_zero() {
    int i = blockIdx.x * blockDim.x + threadIdx.x;
    if (i < NIMG * 4096) (&g_hist[0][0])[i] = 0u;
    if (i < NIMG) {
        g_preCount[i] = 0;
        g_fbImg[i] = 0;
        g_fbHist[i] = 0;
    }
}

// ---------------- K1: fused pass — 16-wide group skip + hist + prefilter compact --------
__global__ void __launch_bounds__(256) k_fused(const float* __restrict__ c0, const float* __restrict__ c1,
                                               const float* __restrict__ c2, const float* __restrict__ c3,
                                               const float* __restrict__ c4) {
    __shared__ unsigned int sh[1024];
    const float* cls[5] = {c0, c1, c2, c3, c4};
    int b = blockIdx.y;
    int bx = blockIdx.x;
    int l = 0;
    while (bx >= c_CB[l + 1]) l++;
    int chunk = bx - c_CB[l];
    int n = c_LN[l];
    const float* p = cls[l] + (size_t)b * n;
    int log2HW = c_log2HW[l];
    int HWm1 = (1 << log2HW) - 1;
    int aOff = c_aOff[l];
    int tid = threadIdx.x;
    for (int i = tid; i < 1024; i += 256) sh[i] = 0u;
    __syncthreads();

    int base = chunk * 4096 + tid * 16;  // all c_LN are multiples of 16
    if (base < n) {
        float4 V0 = *(const float4*)(p + base);
        float4 V1 = *(const float4*)(p + base + 4);
        float4 V2 = *(const float4*)(p + base + 8);
        float4 V3 = *(const float4*)(p + base + 12);
        float4 V[4] = {V0, V1, V2, V3};
        unsigned int um = 0u;
#pragma unroll
        for (int q = 0; q < 4; q++) {
            um = max(um, orderKey(V[q].x));
            um = max(um, orderKey(V[q].y));
            um = max(um, orderKey(V[q].z));
            um = max(um, orderKey(V[q].w));
        }
        if (um >= PRE_KEY) {
#pragma unroll
            for (int q = 0; q < 4; q++) {
                float fv[4] = {V[q].x, V[q].y, V[q].z, V[q].w};
#pragma unroll
                for (int k = 0; k < 4; k++) {
                    unsigned int u = orderKey(fv[k]);
                    if (u >= PRE_KEY) {
                        atomicAdd(&sh[(u >> 20) - HIST_LO], 1u);
                        int off = base + q * 4 + k;
                        int ch = off >> log2HW;
                        int r = off & HWm1;
                        int a = ch / 90;
                        int c = ch - a * 90;
                        int j = (aOff + r * 9 + a) * 90 + c;
                        int pos = atomicAdd(&g_preCount[b], 1);
                        if (pos < PRE_CAP)
                            g_pre[b][pos] = ((unsigned long long)u << 32) | (unsigned int)(~j);
                    }
                }
            }
        }
    }
    __syncthreads();
    for (int i = tid; i < 1024; i += 256) {
        unsigned int c = sh[i];
        if (c) atomicAdd(&g_hist[b][HIST_LO + i], c);
    }
}

// ---------------- K2: threshold from top 1024 bins; detect fallback needs ----------------
__global__ void __launch_bounds__(1024) k_thresh() {
    __shared__ unsigned int part[1024];
    int b = blockIdx.x;
    int t = threadIdx.x;
    unsigned int h = g_hist[b][4095 - t];
    part[t] = h;
    __syncthreads();
    for (int off = 1; off < 1024; off <<= 1) {
        unsigned int vv = (t >= off) ? part[t - off] : 0u;
        __syncthreads();
        part[t] += vv;
        __syncthreads();
    }
    unsigned int incl = part[t];
    unsigned int excl = incl - h;
    if (excl < TOPK && incl >= TOPK) g_T[b] = 4095 - t;
    if (t == 1023) {
        g_candCount[b] = 0;
        if (incl < TOPK) {
            g_fbHist[b] = 1;
            g_fbImg[b] = 1;
        } else if (g_preCount[b] > PRE_CAP) {
            g_fbImg[b] = 1;
        }
    }
}

// ---------------- K3: fallback full histogram (no-op normally; 4 chunks per block) ------
__global__ void __launch_bounds__(256) k_fb_hist(const float* __restrict__ c0, const float* __restrict__ c1,
                                                 const float* __restrict__ c2, const float* __restrict__ c3,
                                                 const float* __restrict__ c4) {
    int b = blockIdx.y;
    if (!g_fbHist[b]) return;
    __shared__ unsigned int sh[4096];
    const float* cls[5] = {c0, c1, c2, c3, c4};
    int tid = threadIdx.x;
    for (int i = tid; i < 4096; i += 256) sh[i] = 0u;
    __syncthreads();
    for (int q = 0; q < 4; q++) {
        int cid = blockIdx.x * 4 + q;
        if (cid >= 1081) break;
        int l = 0;
        while (cid >= c_CB[l + 1]) l++;
        int chunk = cid - c_CB[l];
        int n = c_LN[l];
        const float* p = cls[l] + (size_t)b * n;
        int base = chunk * 4096;
#pragma unroll
        for (int it = 0; it < 4; it++) {
            int e = base + (it * 256 + tid) * 4;
            if (e < n) {
                float4 v = *(const float4*)(p + e);
                float fv[4] = {v.x, v.y, v.z, v.w};
#pragma unroll
                for (int k = 0; k < 4; k++) {
                    unsigned int u = orderKey(fv[k]);
                    if (u < PRE_KEY) atomicAdd(&sh[u >> 20], 1u);
                }
            }
        }
    }
    __syncthreads();
    for (int i = tid; i < 4096; i += 256) {
        unsigned int c = sh[i];
        if (c) atomicAdd(&g_hist[b][i], c);
    }
}

// ---------------- K4: fallback threshold over all 4096 bins (no-op normally) ------------
__global__ void __launch_bounds__(1024) k_fb_thresh() {
    int b = blockIdx.x;
    if (!g_fbHist[b]) return;
    __shared__ unsigned int part[1024];
    int t = threadIdx.x;
    unsigned int h[4], s = 0;
#pragma unroll
    for (int k = 0; k < 4; k++) {
        h[k] = g_hist[b][4095 - (4 * t + k)];
        s += h[k];
    }
    part[t] = s;
    unsigned int my = s;
    __syncthreads();
    for (int off = 1; off < 1024; off <<= 1) {
        unsigned int vv = (t >= off) ? part[t - off] : 0u;
        __syncthreads();
        part[t] += vv;
        __syncthreads();
    }
    unsigned int incl = part[t];
    unsigned int excl = incl - my;
    if (excl < TOPK && incl >= TOPK) {
        unsigned int run = excl;
#pragma unroll
        for (int k = 0; k < 4; k++) {
            if (run + h[k] >= TOPK) { g_T[b] = 4095 - (4 * t + k); break; }
            run += h[k];
        }
    }
}

// ---------------- K5: compact — staging buffer (fast) or raw rescan (fallback) ----------
#define PRE_BLOCKS (PRE_CAP / 4096)
__global__ void __launch_bounds__(256) k_compact(const float* __restrict__ c0, const float* __restrict__ c1,
                                                 const float* __restrict__ c2, const float* __restrict__ c3,
                                                 const float* __restrict__ c4) {
    int b = blockIdx.y;
    int bx = blockIdx.x;
    int tid = threadIdx.x;
    unsigned int T = g_T[b];
    if (!g_fbImg[b]) {
        if (bx >= PRE_BLOCKS) return;
        int n = g_preCount[b];
        if (n > PRE_CAP) n = PRE_CAP;
#pragma unroll
        for (int it = 0; it < 16; it++) {
            int i = bx * 4096 + it * 256 + tid;
            if (i < n) {
                unsigned long long key = g_pre[b][i];
                if ((unsigned int)(key >> 52) >= T) {
                    int pos = atomicAdd(&g_candCount[b], 1);
                    if (pos < CAND_CAP) g_cand[b][pos] = key;
                }
            }
        }
        return;
    }
    const float* cls[5] = {c0, c1, c2, c3, c4};
    int l = 0;
    while (bx >= c_CB[l + 1]) l++;
    int chunk = bx - c_CB[l];
    int n = c_LN[l];
    const float* p = cls[l] + (size_t)b * n;
    int log2HW = c_log2HW[l];
    int HWm1 = (1 << log2HW) - 1;
    int aOff = c_aOff[l];
    int base = chunk * 4096;
#pragma unroll
    for (int it = 0; it < 4; it++) {
        int e = base + (it * 256 + tid) * 4;
        if (e < n) {
            float4 v = *(const float4*)(p + e);
            float fv[4] = {v.x, v.y, v.z, v.w};
#pragma unroll
            for (int k = 0; k < 4; k++) {
                unsigned int u = orderKey(fv[k]);
                if ((u >> 20) >= T) {
                    int off = e + k;
                    int ch = off >> log2HW;
                    int r = off & HWm1;
                    int a = ch / 90;
                    int c = ch - a * 90;
                    int j = (aOff + r * 9 + a) * 90 + c;
                    int pos = atomicAdd(&g_candCount[b], 1);
                    if (pos < CAND_CAP)
                        g_cand[b][pos] = ((unsigned long long)u << 32) | (unsigned int)(~j);
                }
            }
        }
    }
}

// ---------------- K6: per-image bitonic sort + fused decode ----------------
__global__ void __launch_bounds__(1024) k_sortdec(const float* __restrict__ b0, const float* __restrict__ b1,
                                                  const float* __restrict__ b2, const float* __restrict__ b3,
                                                  const float* __restrict__ b4,
                                                  const float* __restrict__ anchors) {
    extern __shared__ unsigned long long ss[];
    const float* box[5] = {b0, b1, b2, b3, b4};
    int b = blockIdx.x;
    int tid = threadIdx.x;
    int n = g_candCount[b];
    if (n > CAND_CAP) n = CAND_CAP;
    int np = 8192;
    while (np < n) np <<= 1;
    for (int i = tid; i < np; i += 1024) ss[i] = (i < n) ? g_cand[b][i] : 0ull;
    __syncthreads();
    for (int k = 2; k <= np; k <<= 1) {
        for (int j = k >> 1; j > 0; j >>= 1) {
            for (int i = tid; i < np; i += 1024) {
                int l = i ^ j;
                if (l > i) {
                    unsigned long long a = ss[i], c = ss[l];
                    bool desc = ((i & k) == 0);
                    if (desc ? (a < c) : (a > c)) { ss[i] = c; ss[l] = a; }
                }
            }
            __syncthreads();
        }
    }
    // fused decode straight out of smem
    for (int t = tid; t < TOPK; t += 1024) {
        unsigned long long key = ss[t];
        unsigned int u = (unsigned int)(key >> 32);
        int j = (int)(~((unsigned int)key));
        unsigned int bits = (u & 0x80000000u) ? (u & 0x7fffffffu) : ~u;
        float v = __uint_as_float(bits);
        int anchor = j / 90;
        int cls = j - anchor * 90;
        int l;
        if (anchor >= 48960) l = 4;
        else if (anchor >= 48384) l = 3;
        else if (anchor >= 46080) l = 2;
        else if (anchor >= 36864) l = 1;
        else l = 0;
        int idx2 = anchor - c_aOff[l];
        int cell = idx2 / 9;
        int a = idx2 - cell * 9;
        int HW = 1 << c_log2HW[l];
        const float* bp = box[l] + (size_t)b * 36 * HW;
        float ty = bp[(a * 4 + 0) * HW + cell];
        float tx = bp[(a * 4 + 1) * HW + cell];
        float th = bp[(a * 4 + 2) * HW + cell];
        float tw = bp[(a * 4 + 3) * HW + cell];
        const float* an = anchors + (size_t)anchor * 4;
        float a0 = an[0], a1 = an[1], a2 = an[2], a3 = an[3];
        float yca = (a0 + a2) * 0.5f;
        float xca = (a1 + a3) * 0.5f;
        float ha = a2 - a0;
        float wa = a3 - a1;
        float w = expf(tw) * wa;
        float h = expf(th) * ha;
        float yc = ty * ha + yca;
        float xc = tx * wa + xca;
        g_bx[b][t * 4 + 0] = xc - w * 0.5f;
        g_bx[b][t * 4 + 1] = yc - h * 0.5f;
        g_bx[b][t * 4 + 2] = xc + w * 0.5f;
        g_bx[b][t * 4 + 3] = yc + h * 0.5f;
        g_sc[b][t] = 1.0f / (1.0f + expf(-v));
        g_cl[b][t] = cls;
    }
}

// ---------------- K7: warp-serial lazy NMS (no block barriers in selection loop) --------
// smem layout:
//   [0,      80000)  float4 sb[5000]      offset boxes
//   [80000, 100000)  float  sar[5000]     areas
//   [100000,101600)  float4 selB[100]
//   [101600,102000)  float  selA[100]
//   [102000,102400)  int    ssel[100]
//   [102400,102528)  float  warpmax[32]
//   [102528]         float  s_off
//   [102532]         int    s_nsel
#define NMS_SMEM 102656
__global__ void __launch_bounds__(1024) k_nms(float* __restrict__ out, const float* __restrict__ scales) {
    extern __shared__ char sm[];
    float4* sb     = (float4*)sm;
    float* sar     = (float*)(sm + 80000);
    float4* selB   = (float4*)(sm + 100000);
    float* selA    = (float*)(sm + 101600);
    int* ssel      = (int*)(sm + 102000);
    float* warpmax = (float*)(sm + 102400);
    float* s_off   = (float*)(sm + 102528);
    int* s_nsel    = (int*)(sm + 102532);

    int b = blockIdx.x;
    int tid = threadIdx.x;
    int lane = tid & 31;
    int wid = tid >> 5;

    // Phase A: max over all decoded coords
    float m = -3.4e38f;
    for (int i = tid; i < TOPK * 4; i += 1024) m = fmaxf(m, g_bx[b][i]);
#pragma unroll
    for (int o = 16; o > 0; o >>= 1) m = fmaxf(m, __shfl_xor_sync(FULLW, m, o));
    if (lane == 0) warpmax[wid] = m;
    __syncthreads();
    if (tid < 32) {
        float v = warpmax[tid];
#pragma unroll
        for (int o = 16; o > 0; o >>= 1) v = fmaxf(v, __shfl_xor_sync(FULLW, v, o));
        if (tid == 0) *s_off = v + 1.0f;
    }
    __syncthreads();
    float offBase = *s_off;

    // Phase B: offset boxes + areas
    for (int t = tid; t < TOPK; t += 1024) {
        float x1 = g_bx[b][t * 4 + 0];
        float y1 = g_bx[b][t * 4 + 1];
        float x2 = g_bx[b][t * 4 + 2];
        float y2 = g_bx[b][t * 4 + 3];
        float off = (float)g_cl[b][t] * offBase;
        float4 bb = make_float4(x1 + off, y1 + off, x2 + off, y2 + off);
        sb[t] = bb;
        sar[t] = (bb.z - bb.x) * (bb.w - bb.y);
    }
    __syncthreads();

    // Phase C: warp 0 runs the whole greedy loop
    if (tid < 32) {
        int cand = lane;
        bool alive = true;
        int nextPos = 32;
        int k = 0;
        float4 cb = sb[cand];
        float ca = sar[cand];
        int nsel = 0;
        for (int it = 0; it < NDET; it++) {
            // find next survivor (refill all lanes when frontier exhausted)
            int selPos = -1;
            for (;;) {
                unsigned int am = __ballot_sync(FULLW, alive);
                if (am) {
                    int c = alive ? cand : 0x7fffffff;
#pragma unroll
                    for (int o = 16; o > 0; o >>= 1) c = min(c, __shfl_xor_sync(FULLW, c, o));
                    selPos = c;
                    break;
                }
                if (nextPos >= TOPK) break;
                cand = nextPos + lane;
                nextPos += 32;
                alive = (cand < TOPK);
                if (alive) {
                    cb = sb[cand];
                    ca = sar[cand];
                    // test vs all previously selected
                    for (int j = 0; j < k; j++) {
                        float4 bj = selB[j];
                        float aj = selA[j];
                        float xx1 = fmaxf(bj.x, cb.x);
                        float yy1 = fmaxf(bj.y, cb.y);
                        float xx2 = fminf(bj.z, cb.z);
                        float yy2 = fminf(bj.w, cb.w);
                        float inter = fmaxf(xx2 - xx1, 0.0f) * fmaxf(yy2 - yy1, 0.0f);
                        float iou = inter / (ca + aj - inter);
                        if (iou > 0.5f) { alive = false; break; }
                    }
                }
            }
            if (selPos < 0) break;
            // broadcast selected box from owner lane
            unsigned int ownm = __ballot_sync(FULLW, alive && cand == selPos);
            int owner = __ffs(ownm) - 1;
            float bix = __shfl_sync(FULLW, cb.x, owner);
            float biy = __shfl_sync(FULLW, cb.y, owner);
            float biz = __shfl_sync(FULLW, cb.z, owner);
            float biw = __shfl_sync(FULLW, cb.w, owner);
            float ai  = __shfl_sync(FULLW, ca, owner);
            if (lane == owner) alive = false;
            if (lane == 0) {
                ssel[it] = selPos;
                selB[k] = make_float4(bix, biy, biz, biw);
                selA[k] = ai;
            }
            k++;
            nsel = it + 1;
            __syncwarp(FULLW);
            // incremental suppression: test alive frontier lanes vs new box
            if (alive) {
                float xx1 = fmaxf(bix, cb.x);
                float yy1 = fmaxf(biy, cb.y);
                float xx2 = fminf(biz, cb.z);
                float yy2 = fminf(biw, cb.w);
                float inter = fmaxf(xx2 - xx1, 0.0f) * fmaxf(yy2 - yy1, 0.0f);
                float iou = inter / (ca + ai - inter);
                if (iou > 0.5f) alive = false;
            }
        }
        if (lane == 0) *s_nsel = nsel;
    }
    __syncthreads();

    // Phase D: write output
    if (tid < NDET) {
        float* o = out + ((size_t)b * NDET + tid) * 6;
        if (tid < *s_nsel) {
            int i = ssel[tid];
            float x1 = g_bx[b][i * 4 + 0];
            float y1 = g_bx[b][i * 4 + 1];
            float x2 = g_bx[b][i * 4 + 2];
            float y2 = g_bx[b][i * 4 + 3];
            float sc = g_sc[b][i];
            float cl = (float)g_cl[b][i] + 1.0f;
            float s = scales[b];
            o[0] = x1 * s;
            o[1] = y1 * s;
            o[2] = (x2 - x1) * s;
            o[3] = (y2 - y1) * s;
            o[4] = sc;
            o[5] = cl;
        } else {
            o[0] = 0.0f; o[1] = 0.0f; o[2] = 0.0f;
            o[3] = 0.0f; o[4] = 0.0f; o[5] = 0.0f;
        }
    }
}

// ---------------- host ----------------
extern "C" void kernel_launch(void* const* d_in, const int* in_sizes, int n_in,
                              void* d_out, int out_size) {
    const float* cls[5] = {nullptr, nullptr, nullptr, nullptr, nullptr};
    const float* box[5] = {nullptr, nullptr, nullptr, nullptr, nullptr};
    const float* scales = nullptr;
    const float* anchors = nullptr;
    static const int clsSizes[5] = {26542080, 6635520, 1658880, 414720, 103680};
    static const int boxSizes[5] = {1179648, 294912, 73728, 18432, 4608};
    for (int i = 0; i < n_in; i++) {
        int s = in_sizes[i];
        const float* p = (const float*)d_in[i];
        if (s == 8) { scales = p; continue; }
        if (s == 196416) { anchors = p; continue; }
        for (int l = 0; l < 5; l++) {
            if (s == clsSizes[l]) cls[l] = p;
            else if (s == boxSizes[l]) box[l] = p;
        }
    }

    cudaFuncSetAttribute(k_sortdec, cudaFuncAttributeMaxDynamicSharedMemorySize, CAND_CAP * 8);
    cudaFuncSetAttribute(k_nms, cudaFuncAttributeMaxDynamicSharedMemorySize, NMS_SMEM);

    k_zero<<<(NIMG * 4096 + 1023) / 1024, 1024>>>();
    k_fused<<<dim3(1081, NIMG), 256>>>(cls[0], cls[1], cls[2], cls[3], cls[4]);
    k_thresh<<<NIMG, 1024>>>();
    k_fb_hist<<<dim3(271, NIMG), 256>>>(cls[0], cls[1], cls[2], cls[3], cls[4]);
    k_fb_thresh<<<NIMG, 1024>>>();
    k_compact<<<dim3(1081, NIMG), 256>>>(cls[0], cls[1], cls[2], cls[3], cls[4]);
    k_sortdec<<<NIMG, 1024, CAND_CAP * 8>>>(box[0], box[1], box[2], box[3], box[4], anchors);
    k_nms<<<NIMG, 1024, NMS_SMEM>>>((float*)d_out, scales);
}

// round 4
// speedup vs baseline: 1.8101x; 1.0619x over previous
#include <cuda_runtime.h>
#include <cstdint>
#include <cstddef>

#define NIMG 8
#define TOPK 5000
#define NDET 100
#define PRE_CAP 49152
#define CAND_CAP 16384
#define PRE_KEY 0xC0200000u   /* orderKey(2.5f) */
#define HIST_LO 3072
#define FULLW 0xffffffffu

// ---------------- scratch (device globals; no allocation) ----------------
__device__ unsigned int       g_hist[NIMG][4096];
__device__ int                g_preCount[NIMG];
__device__ unsigned long long g_pre[NIMG][PRE_CAP];

__constant__ int c_LN[5]     = {3317760, 829440, 207360, 51840, 12960};
__constant__ int c_CB[6]     = {0, 810, 1013, 1064, 1077, 1081};
__constant__ int c_log2HW[5] = {12, 10, 8, 6, 4};
__constant__ int c_aOff[5]   = {0, 36864, 46080, 48384, 48960};

__device__ __forceinline__ unsigned int orderKey(float f) {
    unsigned int b = __float_as_uint(f);
    return (b & 0x80000000u) ? ~b : (b | 0x80000000u);
}

// reference flattened index j -> decoded original box + class, given box tensors/anchors
struct DecOut { float x1, y1, x2, y2; int cls; };
__device__ __forceinline__ DecOut decode_j(int j, int b,
                                           const float* const* box, const float* anchors) {
    int anchor = j / 90;
    int cls = j - anchor * 90;
    int l;
    if (anchor >= 48960) l = 4;
    else if (anchor >= 48384) l = 3;
    else if (anchor >= 46080) l = 2;
    else if (anchor >= 36864) l = 1;
    else l = 0;
    int idx2 = anchor - c_aOff[l];
    int cell = idx2 / 9;
    int a = idx2 - cell * 9;
    int HW = 1 << c_log2HW[l];
    const float* bp = box[l] + (size_t)b * 36 * HW;
    float ty = bp[(a * 4 + 0) * HW + cell];
    float tx = bp[(a * 4 + 1) * HW + cell];
    float th = bp[(a * 4 + 2) * HW + cell];
    float tw = bp[(a * 4 + 3) * HW + cell];
    const float* an = anchors + (size_t)anchor * 4;
    float a0 = an[0], a1 = an[1], a2 = an[2], a3 = an[3];
    float yca = (a0 + a2) * 0.5f;
    float xca = (a1 + a3) * 0.5f;
    float ha = a2 - a0;
    float wa = a3 - a1;
    float w = expf(tw) * wa;
    float h = expf(th) * ha;
    float yc = ty * ha + yca;
    float xc = tx * wa + xca;
    DecOut o;
    o.x1 = xc - w * 0.5f;
    o.y1 = yc - h * 0.5f;
    o.x2 = xc + w * 0.5f;
    o.y2 = yc + h * 0.5f;
    o.cls = cls;
    return o;
}

// ---------------- K0: reset scratch ----------------
__global__ void k_zero() {
    int i = blockIdx.x * blockDim.x + threadIdx.x;
    if (i < NIMG * 4096) (&g_hist[0][0])[i] = 0u;
    if (i < NIMG) g_preCount[i] = 0;
}

// ---------------- K1: fused scan — 16-wide group skip + hist + prefilter compact --------
__global__ void __launch_bounds__(256) k_fused(const float* __restrict__ c0, const float* __restrict__ c1,
                                               const float* __restrict__ c2, const float* __restrict__ c3,
                                               const float* __restrict__ c4) {
    __shared__ unsigned int sh[1024];
    const float* cls[5] = {c0, c1, c2, c3, c4};
    int b = blockIdx.y;
    int bx = blockIdx.x;
    int l = 0;
    while (bx >= c_CB[l + 1]) l++;
    int chunk = bx - c_CB[l];
    int n = c_LN[l];
    const float* p = cls[l] + (size_t)b * n;
    int log2HW = c_log2HW[l];
    int HWm1 = (1 << log2HW) - 1;
    int aOff = c_aOff[l];
    int tid = threadIdx.x;
    for (int i = tid; i < 1024; i += 256) sh[i] = 0u;
    __syncthreads();

    int base = chunk * 4096 + tid * 16;  // all c_LN are multiples of 16
    if (base < n) {
        float4 V0 = *(const float4*)(p + base);
        float4 V1 = *(const float4*)(p + base + 4);
        float4 V2 = *(const float4*)(p + base + 8);
        float4 V3 = *(const float4*)(p + base + 12);
        float4 V[4] = {V0, V1, V2, V3};
        unsigned int um = 0u;
#pragma unroll
        for (int q = 0; q < 4; q++) {
            um = max(um, orderKey(V[q].x));
            um = max(um, orderKey(V[q].y));
            um = max(um, orderKey(V[q].z));
            um = max(um, orderKey(V[q].w));
        }
        if (um >= PRE_KEY) {
#pragma unroll
            for (int q = 0; q < 4; q++) {
                float fv[4] = {V[q].x, V[q].y, V[q].z, V[q].w};
#pragma unroll
                for (int k = 0; k < 4; k++) {
                    unsigned int u = orderKey(fv[k]);
                    if (u >= PRE_KEY) {
                        atomicAdd(&sh[(u >> 20) - HIST_LO], 1u);
                        int off = base + q * 4 + k;
                        int ch = off >> log2HW;
                        int r = off & HWm1;
                        int a = ch / 90;
                        int c = ch - a * 90;
                        int j = (aOff + r * 9 + a) * 90 + c;
                        // warp-aggregated global atomic
                        unsigned int mAct = __activemask();
                        int lane = threadIdx.x & 31;
                        int ldr = __ffs(mAct) - 1;
                        int rank = __popc(mAct & ((1u << lane) - 1u));
                        int bas;
                        if (lane == ldr) bas = atomicAdd(&g_preCount[b], __popc(mAct));
                        bas = __shfl_sync(mAct, bas, ldr);
                        int pos = bas + rank;
                        if (pos < PRE_CAP)
                            g_pre[b][pos] = ((unsigned long long)u << 32) | (unsigned int)(~j);
                    }
                }
            }
        }
    }
    __syncthreads();
    for (int i = tid; i < 1024; i += 256) {
        unsigned int c = sh[i];
        if (c) atomicAdd(&g_hist[b][HIST_LO + i], c);
    }
}

// ---------------- K2: per-image megakernel — thresh/compact/sort/decode/NMS/output ------
// smem layout (bytes):
//   [0,      131072)  ull  ss[16384]         sort keys
//   [40960,  120960)  float4 sbx[5000]       boxes (written AFTER sort; overlaps dead keys)
//                     (also reused pre-sort as fallback hist uint[4096])
//   [120960, 140960)  float sar[5000]        areas
//   [140960, 145056)  uint part[1024]        scan buffer
//   [145056, 145184)  float warpmax[32]
//   [145184, 145216)  scalars
//   [145216, 146816)  float4 selB[100]
//   [146816, 147216)  float selA[100]
//   [147216, 147616)  int ssel[100]
#define MEGA_SMEM 147712
__global__ void __launch_bounds__(1024) k_mega(const float* __restrict__ c0, const float* __restrict__ c1,
                                               const float* __restrict__ c2, const float* __restrict__ c3,
                                               const float* __restrict__ c4,
                                               const float* __restrict__ b0, const float* __restrict__ b1,
                                               const float* __restrict__ b2, const float* __restrict__ b3,
                                               const float* __restrict__ b4,
                                               const float* __restrict__ anchors,
                                               const float* __restrict__ scales,
                                               float* __restrict__ out) {
    extern __shared__ char sm[];
    unsigned long long* ss = (unsigned long long*)sm;
    float4* sbx    = (float4*)(sm + 40960);
    float* sar     = (float*)(sm + 120960);
    unsigned int* part = (unsigned int*)(sm + 140960);
    float* warpmax = (float*)(sm + 145056);
    int* s_T       = (int*)(sm + 145184);
    int* s_fbImg   = (int*)(sm + 145188);
    int* s_cnt     = (int*)(sm + 145192);
    int* s_n       = (int*)(sm + 145196);
    float* s_off   = (float*)(sm + 145200);
    int* s_nsel    = (int*)(sm + 145204);
    float4* selB   = (float4*)(sm + 145216);
    float* selA    = (float*)(sm + 146816);
    int* ssel      = (int*)(sm + 147216);

    const float* cls[5] = {c0, c1, c2, c3, c4};
    const float* box[5] = {b0, b1, b2, b3, b4};
    int b = blockIdx.x;
    int tid = threadIdx.x;
    int lane = tid & 31;
    int wid = tid >> 5;

    // ---- Phase 1: threshold from top-1024 bins ----
    {
        unsigned int h = g_hist[b][4095 - tid];
        part[tid] = h;
        __syncthreads();
        for (int off = 1; off < 1024; off <<= 1) {
            unsigned int vv = (tid >= off) ? part[tid - off] : 0u;
            __syncthreads();
            part[tid] += vv;
            __syncthreads();
        }
        unsigned int incl = part[tid];
        unsigned int excl = incl - h;
        if (excl < TOPK && incl >= TOPK) *s_T = 4095 - tid;
        if (tid == 1023) {
            int fbHist = (incl < TOPK) ? 1 : 0;
            *s_fbImg = (fbHist || g_preCount[b] > PRE_CAP) ? 1 : 0;
            if (fbHist) *s_fbImg = 2;  // 2 => also need full histogram
            *s_cnt = 0;
        }
        __syncthreads();
    }

    // ---- Phase 1b: fallback full histogram + re-threshold (normally skipped) ----
    if (*s_fbImg == 2) {
        unsigned int* fh = (unsigned int*)(sm + 40960); // 16KB temp (pre-decode region)
        for (int i = tid; i < 4096; i += 1024) fh[i] = g_hist[b][i];
        __syncthreads();
        for (int l = 0; l < 5; l++) {
            int n = c_LN[l];
            const float* p = cls[l] + (size_t)b * n;
            for (int e = tid * 4; e < n; e += 4096) {
                float4 v = *(const float4*)(p + e);
                float fv[4] = {v.x, v.y, v.z, v.w};
#pragma unroll
                for (int k = 0; k < 4; k++) {
                    unsigned int u = orderKey(fv[k]);
                    if (u < PRE_KEY) atomicAdd(&fh[u >> 20], 1u);
                }
            }
        }
        __syncthreads();
        unsigned int h[4], s = 0;
#pragma unroll
        for (int k = 0; k < 4; k++) {
            h[k] = fh[4095 - (4 * tid + k)];
            s += h[k];
        }
        part[tid] = s;
        unsigned int my = s;
        __syncthreads();
        for (int off = 1; off < 1024; off <<= 1) {
            unsigned int vv = (tid >= off) ? part[tid - off] : 0u;
            __syncthreads();
            part[tid] += vv;
            __syncthreads();
        }
        unsigned int incl = part[tid];
        unsigned int excl = incl - my;
        if (excl < TOPK && incl >= TOPK) {
            unsigned int run = excl;
#pragma unroll
            for (int k = 0; k < 4; k++) {
                if (run + h[k] >= TOPK) { *s_T = 4095 - (4 * tid + k); break; }
                run += h[k];
            }
        }
        __syncthreads();
    }
    unsigned int T = (unsigned int)*s_T;

    // ---- Phase 2: compact candidates into ss ----
    if (*s_fbImg == 0) {
        int pc = g_preCount[b];
        if (pc > PRE_CAP) pc = PRE_CAP;
        for (int i = tid; i < pc; i += 1024) {
            unsigned long long key = g_pre[b][i];
            if ((unsigned int)(key >> 52) >= T) {
                int pos = atomicAdd(s_cnt, 1);
                if (pos < CAND_CAP) ss[pos] = key;
            }
        }
    } else {
        for (int l = 0; l < 5; l++) {
            int n = c_LN[l];
            const float* p = cls[l] + (size_t)b * n;
            int log2HW = c_log2HW[l];
            int HWm1 = (1 << log2HW) - 1;
            int aOff = c_aOff[l];
            for (int e = tid * 4; e < n; e += 4096) {
                float4 v = *(const float4*)(p + e);
                float fv[4] = {v.x, v.y, v.z, v.w};
#pragma unroll
                for (int k = 0; k < 4; k++) {
                    unsigned int u = orderKey(fv[k]);
                    if ((u >> 20) >= T) {
                        int off = e + k;
                        int ch = off >> log2HW;
                        int r = off & HWm1;
                        int a = ch / 90;
                        int c = ch - a * 90;
                        int j = (aOff + r * 9 + a) * 90 + c;
                        int pos = atomicAdd(s_cnt, 1);
                        if (pos < CAND_CAP)
                            ss[pos] = ((unsigned long long)u << 32) | (unsigned int)(~j);
                    }
                }
            }
        }
    }
    __syncthreads();
    if (tid == 0) {
        int n = *s_cnt;
        *s_n = (n > CAND_CAP) ? CAND_CAP : n;
    }
    __syncthreads();
    int n = *s_n;
    int np = (n <= 8192) ? 8192 : 16384;

    // ---- Phase 3: bitonic sort desc ----
    for (int i = n + tid; i < np; i += 1024) ss[i] = 0ull;
    __syncthreads();
    for (int k = 2; k <= np; k <<= 1) {
        for (int j = k >> 1; j > 0; j >>= 1) {
            for (int i = tid; i < np; i += 1024) {
                int l = i ^ j;
                if (l > i) {
                    unsigned long long a = ss[i], c = ss[l];
                    bool desc = ((i & k) == 0);
                    if (desc ? (a < c) : (a > c)) { ss[i] = c; ss[l] = a; }
                }
            }
            __syncthreads();
        }
    }

    // ---- Phase 4: decode top-5000 into sbx (original boxes) ----
    for (int t = tid; t < TOPK; t += 1024) {
        unsigned long long key = ss[t];
        int j = (int)(~((unsigned int)key));
        DecOut d = decode_j(j, b, box, anchors);
        sbx[t] = make_float4(d.x1, d.y1, d.x2, d.y2);
    }
    __syncthreads();

    // ---- Phase 5: offset base = max coord + 1 ----
    {
        float m = -3.4e38f;
        for (int i = tid; i < TOPK; i += 1024) {
            float4 v = sbx[i];
            m = fmaxf(fmaxf(m, fmaxf(v.x, v.y)), fmaxf(v.z, v.w));
        }
#pragma unroll
        for (int o = 16; o > 0; o >>= 1) m = fmaxf(m, __shfl_xor_sync(FULLW, m, o));
        if (lane == 0) warpmax[wid] = m;
        __syncthreads();
        if (tid < 32) {
            float v = warpmax[tid];
#pragma unroll
            for (int o = 16; o > 0; o >>= 1) v = fmaxf(v, __shfl_xor_sync(FULLW, v, o));
            if (tid == 0) *s_off = v + 1.0f;
        }
        __syncthreads();
    }
    float offBase = *s_off;

    // ---- Phase 6: offset boxes in place + areas ----
    for (int t = tid; t < TOPK; t += 1024) {
        unsigned long long key = ss[t];
        int j = (int)(~((unsigned int)key));
        int cl = j % 90;
        float off = (float)cl * offBase;
        float4 v = sbx[t];
        float4 bb = make_float4(v.x + off, v.y + off, v.z + off, v.w + off);
        sbx[t] = bb;
        sar[t] = (bb.z - bb.x) * (bb.w - bb.y);
    }
    __syncthreads();

    // ---- Phase 7: warp-serial lazy NMS (warp 0 only) ----
    if (tid < 32) {
        int cand = lane;
        bool alive = true;
        int nextPos = 32;
        int k = 0;
        float4 cb = sbx[cand];
        float ca = sar[cand];
        int nsel = 0;
        for (int it = 0; it < NDET; it++) {
            int selPos = -1;
            for (;;) {
                unsigned int am = __ballot_sync(FULLW, alive);
                if (am) {
                    int c = alive ? cand : 0x7fffffff;
#pragma unroll
                    for (int o = 16; o > 0; o >>= 1) c = min(c, __shfl_xor_sync(FULLW, c, o));
                    selPos = c;
                    break;
                }
                if (nextPos >= TOPK) break;
                cand = nextPos + lane;
                nextPos += 32;
                alive = (cand < TOPK);
                if (alive) {
                    cb = sbx[cand];
                    ca = sar[cand];
                    for (int j = 0; j < k; j++) {
                        float4 bj = selB[j];
                        float aj = selA[j];
                        float xx1 = fmaxf(bj.x, cb.x);
                        float yy1 = fmaxf(bj.y, cb.y);
                        float xx2 = fminf(bj.z, cb.z);
                        float yy2 = fminf(bj.w, cb.w);
                        float inter = fmaxf(xx2 - xx1, 0.0f) * fmaxf(yy2 - yy1, 0.0f);
                        float iou = inter / (ca + aj - inter);
                        if (iou > 0.5f) { alive = false; break; }
                    }
                }
            }
            if (selPos < 0) break;
            unsigned int ownm = __ballot_sync(FULLW, alive && cand == selPos);
            int owner = __ffs(ownm) - 1;
            float bix = __shfl_sync(FULLW, cb.x, owner);
            float biy = __shfl_sync(FULLW, cb.y, owner);
            float biz = __shfl_sync(FULLW, cb.z, owner);
            float biw = __shfl_sync(FULLW, cb.w, owner);
            float ai  = __shfl_sync(FULLW, ca, owner);
            if (lane == owner) alive = false;
            if (lane == 0) {
                ssel[it] = selPos;
                selB[k] = make_float4(bix, biy, biz, biw);
                selA[k] = ai;
            }
            k++;
            nsel = it + 1;
            __syncwarp(FULLW);
            if (alive) {
                float xx1 = fmaxf(bix, cb.x);
                float yy1 = fmaxf(biy, cb.y);
                float xx2 = fminf(biz, cb.z);
                float yy2 = fminf(biw, cb.w);
                float inter = fmaxf(xx2 - xx1, 0.0f) * fmaxf(yy2 - yy1, 0.0f);
                float iou = inter / (ca + ai - inter);
                if (iou > 0.5f) alive = false;
            }
        }
        if (lane == 0) *s_nsel = nsel;
    }
    __syncthreads();

    // ---- Phase 8: output (re-decode selected boxes from global tensors) ----
    if (tid < NDET) {
        float* o = out + ((size_t)b * NDET + tid) * 6;
        if (tid < *s_nsel) {
            int i = ssel[tid];
            unsigned long long key = ss[i];
            unsigned int u = (unsigned int)(key >> 32);
            int j = (int)(~((unsigned int)key));
            unsigned int bits = (u & 0x80000000u) ? (u & 0x7fffffffu) : ~u;
            float val = __uint_as_float(bits);
            DecOut d = decode_j(j, b, box, anchors);
            float s = scales[b];
            o[0] = d.x1 * s;
            o[1] = d.y1 * s;
            o[2] = (d.x2 - d.x1) * s;
            o[3] = (d.y2 - d.y1) * s;
            o[4] = 1.0f / (1.0f + expf(-val));
            o[5] = (float)d.cls + 1.0f;
        } else {
            o[0] = 0.0f; o[1] = 0.0f; o[2] = 0.0f;
            o[3] = 0.0f; o[4] = 0.0f; o[5] = 0.0f;
        }
    }
}

// ---------------- host ----------------
extern "C" void kernel_launch(void* const* d_in, const int* in_sizes, int n_in,
                              void* d_out, int out_size) {
    const float* cls[5] = {nullptr, nullptr, nullptr, nullptr, nullptr};
    const float* box[5] = {nullptr, nullptr, nullptr, nullptr, nullptr};
    const float* scales = nullptr;
    const float* anchors = nullptr;
    static const int clsSizes[5] = {26542080, 6635520, 1658880, 414720, 103680};
    static const int boxSizes[5] = {1179648, 294912, 73728, 18432, 4608};
    for (int i = 0; i < n_in; i++) {
        int s = in_sizes[i];
        const float* p = (const float*)d_in[i];
        if (s == 8) { scales = p; continue; }
        if (s == 196416) { anchors = p; continue; }
        for (int l = 0; l < 5; l++) {
            if (s == clsSizes[l]) cls[l] = p;
            else if (s == boxSizes[l]) box[l] = p;
        }
    }

    cudaFuncSetAttribute(k_mega, cudaFuncAttributeMaxDynamicSharedMemorySize, MEGA_SMEM);

    k_zero<<<(NIMG * 4096 + 1023) / 1024, 1024>>>();
    k_fused<<<dim3(1081, NIMG), 256>>>(cls[0], cls[1], cls[2], cls[3], cls[4]);
    k_mega<<<NIMG, 1024, MEGA_SMEM>>>(cls[0], cls[1], cls[2], cls[3], cls[4],
                                      box[0], box[1], box[2], box[3], box[4],
                                      anchors, scales, (float*)d_out);
}